// round 1
// baseline (speedup 1.0000x reference)
#include <cuda_runtime.h>
#include <cstdint>

// Problem constants
#define B_     4
#define C_     512     // input channels == output channels
#define T_     256
#define H_     64
#define AUX_   256
#define OUT_   512
#define KW_    (C_ + AUX_)   // 768, W row length
#define TH_    (T_ * H_)     // 16384 tokens per batch (contiguous in x/y for fixed (b,c))
#define MTOT_  (B_ * TH_)    // 65536 tokens

// Tiling for main fused kernel
#define TILE_M 64
#define KC     32
#define NC     128
#define NTH    256
#define ZS     513          // zbuf row stride (pad to avoid bank conflicts)
#define WSS    132          // Ws row stride (pad, multiple of 4 for float4 alignment)

// Per-batch projection of speaker embedding through W[:, C_:] plus bias.
__device__ float g_sproj[B_ * OUT_];

__global__ void sproj_kernel(const float* __restrict__ s,
                             const float* __restrict__ W,
                             const float* __restrict__ bias) {
    __shared__ float ss[AUX_];
    int b = blockIdx.x;
    int tid = threadIdx.x;
    if (tid < AUX_) ss[tid] = s[b * AUX_ + tid];
    __syncthreads();
    for (int o = tid; o < OUT_; o += blockDim.x) {
        const float* wr = W + (size_t)o * KW_ + C_;
        float acc = bias[o];
#pragma unroll 8
        for (int k = 0; k < AUX_; ++k) acc += ss[k] * wr[k];
        g_sproj[b * OUT_ + o] = acc;
    }
}

// Fused: z = xt @ W[:, :512]^T + sproj[b]; p = prelu(z); LN over OUT;
// y = x + LN; stored in (b,c,t,h) layout (same as x).
__global__ __launch_bounds__(NTH, 1)
void fused_kernel(const float* __restrict__ x,
                  const float* __restrict__ W,
                  const float* __restrict__ prelu2_a,
                  const float* __restrict__ lnw,
                  const float* __restrict__ lnb,
                  float* __restrict__ out) {
    extern __shared__ float sm[];
    float* zbuf = sm;                       // [TILE_M][ZS]
    float* As   = zbuf + TILE_M * ZS;       // [KC][TILE_M]
    float* Ws   = As + KC * TILE_M;         // [KC][WSS]
    float* mu_s = Ws + KC * WSS;            // [TILE_M]
    float* rs_s = mu_s + TILE_M;            // [TILE_M]

    const int tid = threadIdx.x;
    const int m0 = blockIdx.x * TILE_M;     // global token index
    const int bi = m0 / TH_;
    const int mb = m0 % TH_;                // offset within (t,h) plane
    const float* xbase = x + (size_t)bi * C_ * TH_ + mb;

    const int tid_m = tid >> 5;             // 0..7  (warp id -> 8 token rows)
    const int tid_n = tid & 31;             // 0..31 (lane -> 4 output cols)

    // ---- GEMM: z[64][512], N-chunked by 128 ----
    for (int n0 = 0; n0 < OUT_; n0 += NC) {
        float acc[8][4];
#pragma unroll
        for (int i = 0; i < 8; ++i)
#pragma unroll
            for (int j = 0; j < 4; ++j) acc[i][j] = 0.f;

        for (int kc = 0; kc < C_; kc += KC) {
            __syncthreads();
            // Load A tile: As[k][m] = x[bi][kc+k][token m], contiguous over m.
            {
                int q = tid;
#pragma unroll
                for (int r = 0; r < 2; ++r, q += NTH) {
                    int k = q >> 4, mv = q & 15;
                    *(float4*)&As[k * TILE_M + mv * 4] =
                        *(const float4*)(xbase + (size_t)(kc + k) * TH_ + mv * 4);
                }
            }
            // Load W tile transposed: Ws[k][n] = W[n0+n][kc+k].
            {
                int q = tid;
#pragma unroll
                for (int r = 0; r < 4; ++r, q += NTH) {
                    int n = q >> 3, kv = q & 7;
                    float4 w = *(const float4*)(W + (size_t)(n0 + n) * KW_ + kc + kv * 4);
                    Ws[(kv * 4 + 0) * WSS + n] = w.x;
                    Ws[(kv * 4 + 1) * WSS + n] = w.y;
                    Ws[(kv * 4 + 2) * WSS + n] = w.z;
                    Ws[(kv * 4 + 3) * WSS + n] = w.w;
                }
            }
            __syncthreads();
#pragma unroll
            for (int k = 0; k < KC; ++k) {
                float4 a0 = *(float4*)&As[k * TILE_M + tid_m * 8];
                float4 a1 = *(float4*)&As[k * TILE_M + tid_m * 8 + 4];
                float4 wv = *(float4*)&Ws[k * WSS + tid_n * 4];
                float a[8] = {a0.x, a0.y, a0.z, a0.w, a1.x, a1.y, a1.z, a1.w};
                float w[4] = {wv.x, wv.y, wv.z, wv.w};
#pragma unroll
                for (int i = 0; i < 8; ++i)
#pragma unroll
                    for (int j = 0; j < 4; ++j) acc[i][j] += a[i] * w[j];
            }
        }
        // Store z chunk to SMEM (+ per-batch sproj)
        float4 sp = *(const float4*)&g_sproj[bi * OUT_ + n0 + tid_n * 4];
        float spv[4] = {sp.x, sp.y, sp.z, sp.w};
#pragma unroll
        for (int i = 0; i < 8; ++i) {
            int m = tid_m * 8 + i;
#pragma unroll
            for (int j = 0; j < 4; ++j)
                zbuf[m * ZS + n0 + tid_n * 4 + j] = acc[i][j] + spv[j];
        }
    }
    __syncthreads();

    // ---- Epilogue phase 1: PReLU in-place + LN stats per token ----
    const float a2 = *prelu2_a;
    const int warp = tid >> 5, lane = tid & 31;
    for (int j = warp * 8; j < warp * 8 + 8; ++j) {
        float* zr = &zbuf[j * ZS];
        float sum = 0.f;
        for (int q = lane; q < OUT_; q += 32) {
            float v = zr[q];
            v = (v >= 0.f) ? v : a2 * v;
            zr[q] = v;
            sum += v;
        }
#pragma unroll
        for (int off = 16; off; off >>= 1) sum += __shfl_xor_sync(0xffffffffu, sum, off);
        float mu = sum * (1.f / OUT_);
        float s2 = 0.f;
        for (int q = lane; q < OUT_; q += 32) {
            float d = zr[q] - mu;
            s2 += d * d;
        }
#pragma unroll
        for (int off = 16; off; off >>= 1) s2 += __shfl_xor_sync(0xffffffffu, s2, off);
        if (lane == 0) {
            mu_s[j] = mu;
            rs_s[j] = rsqrtf(s2 * (1.f / OUT_) + 1e-8f);
        }
    }
    __syncthreads();

    // ---- Epilogue phase 2: y = x + (p - mu)*r*lnw + lnb, coalesced along tokens ----
    for (int o = tid; o < OUT_; o += NTH) {
        const float lw = lnw[o], lb = lnb[o];
        const size_t gbase = ((size_t)(bi * C_ + o)) * TH_ + mb;
#pragma unroll 4
        for (int mq = 0; mq < TILE_M; mq += 4) {
            float4 xv = *(const float4*)(x + gbase + mq);
            float4 yv;
            yv.x = xv.x + (zbuf[(mq + 0) * ZS + o] - mu_s[mq + 0]) * rs_s[mq + 0] * lw + lb;
            yv.y = xv.y + (zbuf[(mq + 1) * ZS + o] - mu_s[mq + 1]) * rs_s[mq + 1] * lw + lb;
            yv.z = xv.z + (zbuf[(mq + 2) * ZS + o] - mu_s[mq + 2]) * rs_s[mq + 2] * lw + lb;
            yv.w = xv.w + (zbuf[(mq + 3) * ZS + o] - mu_s[mq + 3]) * rs_s[mq + 3] * lw + lb;
            *(float4*)(out + gbase + mq) = yv;
        }
    }
}

extern "C" void kernel_launch(void* const* d_in, const int* in_sizes, int n_in,
                              void* d_out, int out_size) {
    (void)in_sizes; (void)n_in; (void)out_size;
    const float* x        = (const float*)d_in[0];
    const float* s        = (const float*)d_in[1];
    // d_in[2..4]: prelu1_a, ln1_w, ln1_b -> dead code in reference
    const float* W        = (const float*)d_in[5];
    const float* bias     = (const float*)d_in[6];
    const float* prelu2_a = (const float*)d_in[7];
    const float* ln2_w    = (const float*)d_in[8];
    const float* ln2_b    = (const float*)d_in[9];
    float* out = (float*)d_out;

    size_t smem = (size_t)(TILE_M * ZS + KC * TILE_M + KC * WSS + 2 * TILE_M) * sizeof(float);
    cudaFuncSetAttribute(fused_kernel, cudaFuncAttributeMaxDynamicSharedMemorySize, (int)smem);

    sproj_kernel<<<B_, 256>>>(s, W, bias);
    fused_kernel<<<MTOT_ / TILE_M, NTH, smem>>>(x, W, prelu2_a, ln2_w, ln2_b, out);
}

// round 4
// speedup vs baseline: 2.0934x; 2.0934x over previous
#include <cuda_runtime.h>
#include <cuda_bf16.h>
#include <cstdint>

// ---------------- problem constants ----------------
#define B_     4
#define C_     512
#define TH_    16384
#define MTOT_  (B_ * TH_)     // 65536 tokens
#define KW_    768
#define AUX_   256
#define OUT_   512

// ---------------- GEMM tiling ----------------
#define BM 128
#define BN 128
#define BK 32
#define NS (C_ / BK)          // 16 k-stages
#define NTHR 256
// SMEM stage layout: Ah(8KB) Al(8KB) Wh(10240) Wl(10240) = 36864 B; 3-stage ring
#define ST_A_H  0
#define ST_A_L  8192
#define ST_W_H  16384
#define ST_W_L  26624
#define ST_SZ   36864
#define GEMM_SMEM (3 * ST_SZ)
#define WROWB 80              // padded W row stride (bytes) -> conflict-free ldmatrix

// ---------------- device scratch ----------------
__device__ __align__(16) float g_Z[(size_t)MTOT_ * OUT_];            // 134MB
__device__ __align__(16) __nv_bfloat16 g_Wh[(size_t)OUT_ * C_];      // 512KB
__device__ __align__(16) __nv_bfloat16 g_Wl[(size_t)OUT_ * C_];      // 512KB
__device__ float g_sproj[B_ * OUT_];

// ---------------- asm helpers ----------------
__device__ __forceinline__ uint32_t smem_u32(const void* p) {
    uint32_t a;
    asm("{ .reg .u64 t; cvta.to.shared.u64 t, %1; cvt.u32.u64 %0, t; }" : "=r"(a) : "l"(p));
    return a;
}
__device__ __forceinline__ void cp_async16(uint32_t dst, const void* src) {
    asm volatile("cp.async.cg.shared.global [%0], [%1], 16;" :: "r"(dst), "l"(src) : "memory");
}
#define CP_COMMIT() asm volatile("cp.async.commit_group;" ::: "memory")
#define CP_WAIT(n)  asm volatile("cp.async.wait_group %0;" :: "n"(n) : "memory")

__device__ __forceinline__ void ldm_x4(uint32_t* r, uint32_t addr) {
    asm volatile("ldmatrix.sync.aligned.m8n8.x4.shared.b16 {%0,%1,%2,%3}, [%4];"
                 : "=r"(r[0]), "=r"(r[1]), "=r"(r[2]), "=r"(r[3]) : "r"(addr));
}
__device__ __forceinline__ void ldm_x4_t(uint32_t* r, uint32_t addr) {
    asm volatile("ldmatrix.sync.aligned.m8n8.x4.trans.shared.b16 {%0,%1,%2,%3}, [%4];"
                 : "=r"(r[0]), "=r"(r[1]), "=r"(r[2]), "=r"(r[3]) : "r"(addr));
}
__device__ __forceinline__ void mma16816(float* d, const uint32_t* a, const uint32_t* b) {
    asm volatile(
        "mma.sync.aligned.m16n8k16.row.col.f32.bf16.bf16.f32 "
        "{%0,%1,%2,%3},{%4,%5,%6,%7},{%8,%9},{%0,%1,%2,%3};"
        : "+f"(d[0]), "+f"(d[1]), "+f"(d[2]), "+f"(d[3])
        : "r"(a[0]), "r"(a[1]), "r"(a[2]), "r"(a[3]), "r"(b[0]), "r"(b[1]));
}
__device__ __forceinline__ void sts128(uint32_t dst, uint4 v) {
    asm volatile("st.shared.v4.b32 [%0], {%1,%2,%3,%4};"
                 :: "r"(dst), "r"(v.x), "r"(v.y), "r"(v.z), "r"(v.w) : "memory");
}

// split f: hi = bf16(f), lo = bf16(f - hi)
__device__ __forceinline__ void split8(const float* f, uint4& hi, uint4& lo) {
    unsigned short h[8], l[8];
#pragma unroll
    for (int j = 0; j < 8; ++j) {
        __nv_bfloat16 hb = __float2bfloat16_rn(f[j]);
        __nv_bfloat16 lb = __float2bfloat16_rn(f[j] - __bfloat162float(hb));
        h[j] = __bfloat16_as_ushort(hb);
        l[j] = __bfloat16_as_ushort(lb);
    }
    hi = make_uint4((uint32_t)h[0] | ((uint32_t)h[1] << 16), (uint32_t)h[2] | ((uint32_t)h[3] << 16),
                    (uint32_t)h[4] | ((uint32_t)h[5] << 16), (uint32_t)h[6] | ((uint32_t)h[7] << 16));
    lo = make_uint4((uint32_t)l[0] | ((uint32_t)l[1] << 16), (uint32_t)l[2] | ((uint32_t)l[3] << 16),
                    (uint32_t)l[4] | ((uint32_t)l[5] << 16), (uint32_t)l[6] | ((uint32_t)l[7] << 16));
}

// ---------------- prep kernels ----------------
__global__ void sproj_kernel(const float* __restrict__ s, const float* __restrict__ W,
                             const float* __restrict__ bias) {
    __shared__ float ss[AUX_];
    int b = blockIdx.x, tid = threadIdx.x;
    if (tid < AUX_) ss[tid] = s[b * AUX_ + tid];
    __syncthreads();
    for (int o = tid; o < OUT_; o += blockDim.x) {
        const float* wr = W + (size_t)o * KW_ + C_;
        float acc = bias[o];
#pragma unroll 8
        for (int k = 0; k < AUX_; ++k) acc += ss[k] * wr[k];
        g_sproj[b * OUT_ + o] = acc;
    }
}

__global__ void wprep_kernel(const float* __restrict__ W) {
    int n = blockIdx.x, t = threadIdx.x;
#pragma unroll
    for (int r = 0; r < 2; ++r) {
        int k = t + r * 256;
        float f = W[(size_t)n * KW_ + k];
        __nv_bfloat16 hb = __float2bfloat16_rn(f);
        __nv_bfloat16 lb = __float2bfloat16_rn(f - __bfloat162float(hb));
        g_Wh[(size_t)n * C_ + k] = hb;
        g_Wl[(size_t)n * C_ + k] = lb;
    }
}

// ---------------- GEMM: g_Z[m][n] = sum_k x[k][m] * W[n][k], 3-term bf16 split ----------------
__global__ __launch_bounds__(NTHR, 1)
void gemm_kernel(const float* __restrict__ x) {
    extern __shared__ char smem[];
    const uint32_t sb = smem_u32(smem);
    const int tid = threadIdx.x, lane = tid & 31, wid = tid >> 5;
    const int wm = wid & 3, wn = wid >> 2;            // 4x2 warp grid
    const int mwarp = wm * 32, nwarp = wn * 64;
    const int m0 = blockIdx.y * BM;
    const int n0 = blockIdx.x * BN;
    const int bi = m0 >> 14, mb = m0 & (TH_ - 1);
    const float* xb = x + (size_t)bi * C_ * TH_ + mb;

    // --- loader slot decode (A): slots t, t+256 ---
    const int ka0 = tid >> 4, mo0 = tid & 15;
    const int ka1 = (tid + 256) >> 4, mo1 = (tid + 256) & 15;

    // --- ldmatrix per-lane constant offsets ---
    const int krl = (lane & 7) + ((lane >> 4) & 1) * 8;            // 0..15
    const int mcl = ((lane >> 3) & 1) * 8;
    uint32_t cA[2];
#pragma unroll
    for (int i = 0; i < 2; ++i)
        cA[i] = krl * 256 + (((mwarp + i * 16 + mcl) * 2) ^ ((krl & 7) << 4));
    const int nll = (lane & 7) + ((lane >> 4) & 1) * 8;            // n within 16
    const int kcl = ((lane >> 3) & 1) * 8;
    const uint32_t cB = (nwarp + nll) * WROWB + kcl * 2;

    float acc[2][8][4];
#pragma unroll
    for (int i = 0; i < 2; ++i)
#pragma unroll
        for (int j = 0; j < 8; ++j)
#pragma unroll
            for (int q = 0; q < 4; ++q) acc[i][j][q] = 0.f;

    // ---- helpers as lambdas ----
    auto issue_W = [&](int s) {
        const uint32_t wb = sb + (s % 3) * ST_SZ + ST_W_H;
        const int kk = s * BK;
#pragma unroll
        for (int r = 0; r < 4; ++r) {
            int slot = tid + 256 * r;
            int hl = slot >> 9, n = (slot >> 2) & 127, kc = slot & 3;
            const __nv_bfloat16* src = (hl ? g_Wl : g_Wh) + (size_t)(n0 + n) * C_ + kk + kc * 8;
            cp_async16(wb + hl * (ST_W_L - ST_W_H) + n * WROWB + kc * 16, src);
        }
        CP_COMMIT();
    };
    auto ldg_A = [&](int s, float4* f) {
        const int kk = s * BK;
        const float* r0 = xb + (size_t)(kk + ka0) * TH_ + mo0 * 8;
        const float* r1 = xb + (size_t)(kk + ka1) * TH_ + mo1 * 8;
        f[0] = *(const float4*)r0; f[1] = *(const float4*)(r0 + 4);
        f[2] = *(const float4*)r1; f[3] = *(const float4*)(r1 + 4);
    };
    auto sts_A = [&](int s, const float4* f) {
        const uint32_t ab = sb + (s % 3) * ST_SZ;
        uint4 hi, lo;
        split8((const float*)&f[0], hi, lo);
        uint32_t d0 = ab + ka0 * 256 + ((mo0 ^ (ka0 & 7)) << 4);
        sts128(d0 + ST_A_H, hi); sts128(d0 + ST_A_L, lo);
        split8((const float*)&f[2], hi, lo);
        uint32_t d1 = ab + ka1 * 256 + ((mo1 ^ (ka1 & 7)) << 4);
        sts128(d1 + ST_A_H, hi); sts128(d1 + ST_A_L, lo);
    };

    // ---- prologue: stages 0,1 ----
    {
        float4 f[4];
        ldg_A(0, f); sts_A(0, f); issue_W(0);
        ldg_A(1, f); sts_A(1, f); issue_W(1);
        CP_WAIT(0);
    }
    __syncthreads();

    // ---- mainloop ----
    float4 fr[4];
    for (int s = 0; s < NS; ++s) {
        const bool pf = (s + 2 < NS);
        if (pf) { issue_W(s + 2); ldg_A(s + 2, fr); }

        const uint32_t stb = sb + (s % 3) * ST_SZ;
#pragma unroll
        for (int h16 = 0; h16 < 2; ++h16) {
            uint32_t aH[2][4], aL[2][4];
#pragma unroll
            for (int i = 0; i < 2; ++i) {
                ldm_x4_t(aH[i], stb + ST_A_H + h16 * 16 * 256 + cA[i]);
                ldm_x4_t(aL[i], stb + ST_A_L + h16 * 16 * 256 + cA[i]);
            }
#pragma unroll
            for (int j2 = 0; j2 < 4; ++j2) {
                uint32_t bH[4], bL[4];
                ldm_x4(bH, stb + ST_W_H + h16 * 32 + cB + j2 * (16 * WROWB));
                ldm_x4(bL, stb + ST_W_L + h16 * 32 + cB + j2 * (16 * WROWB));
#pragma unroll
                for (int i = 0; i < 2; ++i)
#pragma unroll
                    for (int jj = 0; jj < 2; ++jj) {
                        float* d = acc[i][j2 * 2 + jj];
                        mma16816(d, aH[i], &bH[jj * 2]);
                        mma16816(d, aL[i], &bH[jj * 2]);
                        mma16816(d, aH[i], &bL[jj * 2]);
                    }
            }
        }
        __syncthreads();
        if (pf) {
            sts_A(s + 2, fr);
            CP_WAIT(1);
        } else {
            CP_WAIT(0);
        }
        __syncthreads();
    }

    // ---- store z (f32, token-major) ----
    const int rbase = m0 + mwarp + (lane >> 2);
    const int cbase = n0 + nwarp + (lane & 3) * 2;
#pragma unroll
    for (int i = 0; i < 2; ++i)
#pragma unroll
        for (int j = 0; j < 8; ++j) {
            float* d = acc[i][j];
            size_t r0 = (size_t)(rbase + i * 16) * OUT_ + cbase + j * 8;
            *(float2*)&g_Z[r0] = make_float2(d[0], d[1]);
            *(float2*)&g_Z[r0 + 8 * OUT_] = make_float2(d[2], d[3]);
        }
}

// ---------------- epilogue: PReLU + LN + residual + transpose ----------------
#define EM 64
#define EZS 516
__global__ __launch_bounds__(256, 1)
void epilogue_kernel(const float* __restrict__ x, const float* __restrict__ prelu2_a,
                     const float* __restrict__ lnw, const float* __restrict__ lnb,
                     float* __restrict__ out) {
    extern __shared__ float zb[];          // [EM][EZS] + mu[64] + rs[64]
    float* mu_s = zb + EM * EZS;
    float* rs_s = mu_s + EM;
    const int tid = threadIdx.x, lane = tid & 31, warp = tid >> 5;
    const int m0 = blockIdx.x * EM;
    const int bi = m0 >> 14, mb = m0 & (TH_ - 1);
    const float a2 = *prelu2_a;
    const float* sp = g_sproj + bi * OUT_;

    // load z + sproj + prelu into SMEM
#pragma unroll
    for (int r = 0; r < 32; ++r) {
        int idx = tid + 256 * r;
        int m = idx >> 7, q4 = idx & 127;
        float4 v = *(const float4*)&g_Z[(size_t)(m0 + m) * OUT_ + q4 * 4];
        float4 spv = *(const float4*)&sp[q4 * 4];
        v.x += spv.x; v.y += spv.y; v.z += spv.z; v.w += spv.w;
        v.x = (v.x >= 0.f) ? v.x : a2 * v.x;
        v.y = (v.y >= 0.f) ? v.y : a2 * v.y;
        v.z = (v.z >= 0.f) ? v.z : a2 * v.z;
        v.w = (v.w >= 0.f) ? v.w : a2 * v.w;
        *(float4*)&zb[m * EZS + q4 * 4] = v;
    }
    __syncthreads();

    // stats: warp handles 8 tokens
    for (int j = warp * 8; j < warp * 8 + 8; ++j) {
        const float* zr = &zb[j * EZS];
        float sum = 0.f, ssq = 0.f;
#pragma unroll
        for (int it = 0; it < 16; ++it) {
            float v = zr[lane + it * 32];
            sum += v; ssq += v * v;
        }
#pragma unroll
        for (int off = 16; off; off >>= 1) {
            sum += __shfl_xor_sync(0xffffffffu, sum, off);
            ssq += __shfl_xor_sync(0xffffffffu, ssq, off);
        }
        if (lane == 0) {
            float mu = sum * (1.f / OUT_);
            mu_s[j] = mu;
            rs_s[j] = rsqrtf(ssq * (1.f / OUT_) - mu * mu + 1e-8f);
        }
    }
    __syncthreads();

    // write out = x + LN(z), coalesced along tokens
    for (int o = tid; o < OUT_; o += 256) {
        const float lw = lnw[o], lb = lnb[o];
        const size_t gbase = ((size_t)(bi * OUT_ + o)) * TH_ + mb;
#pragma unroll 4
        for (int mq = 0; mq < EM; mq += 4) {
            float4 xv = *(const float4*)(x + gbase + mq);
            float4 yv;
            yv.x = xv.x + (zb[(mq + 0) * EZS + o] - mu_s[mq + 0]) * rs_s[mq + 0] * lw + lb;
            yv.y = xv.y + (zb[(mq + 1) * EZS + o] - mu_s[mq + 1]) * rs_s[mq + 1] * lw + lb;
            yv.z = xv.z + (zb[(mq + 2) * EZS + o] - mu_s[mq + 2]) * rs_s[mq + 2] * lw + lb;
            yv.w = xv.w + (zb[(mq + 3) * EZS + o] - mu_s[mq + 3]) * rs_s[mq + 3] * lw + lb;
            *(float4*)(out + gbase + mq) = yv;
        }
    }
}

// ---------------- launch ----------------
extern "C" void kernel_launch(void* const* d_in, const int* in_sizes, int n_in,
                              void* d_out, int out_size) {
    (void)in_sizes; (void)n_in; (void)out_size;
    const float* x        = (const float*)d_in[0];
    const float* s        = (const float*)d_in[1];
    const float* W        = (const float*)d_in[5];
    const float* bias     = (const float*)d_in[6];
    const float* prelu2_a = (const float*)d_in[7];
    const float* ln2_w    = (const float*)d_in[8];
    const float* ln2_b    = (const float*)d_in[9];
    float* out = (float*)d_out;

    cudaFuncSetAttribute(gemm_kernel, cudaFuncAttributeMaxDynamicSharedMemorySize, GEMM_SMEM);
    size_t esm = (size_t)(EM * EZS + 2 * EM) * sizeof(float);
    cudaFuncSetAttribute(epilogue_kernel, cudaFuncAttributeMaxDynamicSharedMemorySize, (int)esm);

    sproj_kernel<<<B_, 256>>>(s, W, bias);
    wprep_kernel<<<OUT_, 256>>>(W);
    dim3 grid(BN == 128 ? OUT_ / BN : 4, MTOT_ / BM);
    gemm_kernel<<<grid, NTHR, GEMM_SMEM>>>(x);
    epilogue_kernel<<<MTOT_ / EM, 256, esm>>>(x, prelu2_a, ln2_w, ln2_b, out);
}

// round 5
// speedup vs baseline: 2.2348x; 1.0675x over previous
#include <cuda_runtime.h>
#include <cuda_bf16.h>
#include <cstdint>

// ---------------- problem constants ----------------
#define B_     4
#define C_     512
#define TH_    16384
#define MTOT_  (B_ * TH_)     // 65536 tokens
#define KW_    768
#define AUX_   256
#define OUT_   512

// ---------------- GEMM tiling ----------------
#define BM 128
#define BN 128
#define BK 32
#define NS (C_ / BK)          // 16 k-stages
#define NTHR 512
#define ST_A_H  0
#define ST_A_L  8192
#define ST_W_H  16384
#define ST_W_L  26624
#define ST_SZ   36864
#define GEMM_SMEM (3 * ST_SZ)
#define WROWB 80

// ---------------- device scratch ----------------
__device__ __align__(16) float g_Z[(size_t)MTOT_ * OUT_];            // 134MB
__device__ __align__(16) __nv_bfloat16 g_Wh[(size_t)OUT_ * C_];
__device__ __align__(16) __nv_bfloat16 g_Wl[(size_t)OUT_ * C_];
__device__ float g_sproj[B_ * OUT_];

// ---------------- asm helpers ----------------
__device__ __forceinline__ uint32_t smem_u32(const void* p) {
    uint32_t a;
    asm("{ .reg .u64 t; cvta.to.shared.u64 t, %1; cvt.u32.u64 %0, t; }" : "=r"(a) : "l"(p));
    return a;
}
__device__ __forceinline__ void cp_async16(uint32_t dst, const void* src) {
    asm volatile("cp.async.cg.shared.global [%0], [%1], 16;" :: "r"(dst), "l"(src) : "memory");
}
#define CP_COMMIT() asm volatile("cp.async.commit_group;" ::: "memory")
#define CP_WAIT(n)  asm volatile("cp.async.wait_group %0;" :: "n"(n) : "memory")

__device__ __forceinline__ void ldm_x4(uint32_t* r, uint32_t addr) {
    asm volatile("ldmatrix.sync.aligned.m8n8.x4.shared.b16 {%0,%1,%2,%3}, [%4];"
                 : "=r"(r[0]), "=r"(r[1]), "=r"(r[2]), "=r"(r[3]) : "r"(addr));
}
__device__ __forceinline__ void ldm_x4_t(uint32_t* r, uint32_t addr) {
    asm volatile("ldmatrix.sync.aligned.m8n8.x4.trans.shared.b16 {%0,%1,%2,%3}, [%4];"
                 : "=r"(r[0]), "=r"(r[1]), "=r"(r[2]), "=r"(r[3]) : "r"(addr));
}
__device__ __forceinline__ void mma16816(float* d, const uint32_t* a, const uint32_t* b) {
    asm volatile(
        "mma.sync.aligned.m16n8k16.row.col.f32.bf16.bf16.f32 "
        "{%0,%1,%2,%3},{%4,%5,%6,%7},{%8,%9},{%0,%1,%2,%3};"
        : "+f"(d[0]), "+f"(d[1]), "+f"(d[2]), "+f"(d[3])
        : "r"(a[0]), "r"(a[1]), "r"(a[2]), "r"(a[3]), "r"(b[0]), "r"(b[1]));
}
__device__ __forceinline__ void sts128(uint32_t dst, uint4 v) {
    asm volatile("st.shared.v4.b32 [%0], {%1,%2,%3,%4};"
                 :: "r"(dst), "r"(v.x), "r"(v.y), "r"(v.z), "r"(v.w) : "memory");
}

__device__ __forceinline__ void split8(const float* f, uint4& hi, uint4& lo) {
    unsigned short h[8], l[8];
#pragma unroll
    for (int j = 0; j < 8; ++j) {
        __nv_bfloat16 hb = __float2bfloat16_rn(f[j]);
        __nv_bfloat16 lb = __float2bfloat16_rn(f[j] - __bfloat162float(hb));
        h[j] = __bfloat16_as_ushort(hb);
        l[j] = __bfloat16_as_ushort(lb);
    }
    hi = make_uint4((uint32_t)h[0] | ((uint32_t)h[1] << 16), (uint32_t)h[2] | ((uint32_t)h[3] << 16),
                    (uint32_t)h[4] | ((uint32_t)h[5] << 16), (uint32_t)h[6] | ((uint32_t)h[7] << 16));
    lo = make_uint4((uint32_t)l[0] | ((uint32_t)l[1] << 16), (uint32_t)l[2] | ((uint32_t)l[3] << 16),
                    (uint32_t)l[4] | ((uint32_t)l[5] << 16), (uint32_t)l[6] | ((uint32_t)l[7] << 16));
}

// ---------------- prep kernels ----------------
__global__ void sproj_kernel(const float* __restrict__ s, const float* __restrict__ W,
                             const float* __restrict__ bias) {
    __shared__ float ss[AUX_];
    int b = blockIdx.x, tid = threadIdx.x;
    if (tid < AUX_) ss[tid] = s[b * AUX_ + tid];
    __syncthreads();
    for (int o = tid; o < OUT_; o += blockDim.x) {
        const float* wr = W + (size_t)o * KW_ + C_;
        float acc = bias[o];
#pragma unroll 8
        for (int k = 0; k < AUX_; ++k) acc += ss[k] * wr[k];
        g_sproj[b * OUT_ + o] = acc;
    }
}

__global__ void wprep_kernel(const float* __restrict__ W) {
    int n = blockIdx.x, t = threadIdx.x;
#pragma unroll
    for (int r = 0; r < 2; ++r) {
        int k = t + r * 256;
        float f = W[(size_t)n * KW_ + k];
        __nv_bfloat16 hb = __float2bfloat16_rn(f);
        __nv_bfloat16 lb = __float2bfloat16_rn(f - __bfloat162float(hb));
        g_Wh[(size_t)n * C_ + k] = hb;
        g_Wl[(size_t)n * C_ + k] = lb;
    }
}

// ---------------- GEMM: g_Z[m][n] = sum_k x[k][m]*W[n][k], 3-term bf16 split ----------------
__global__ __launch_bounds__(NTHR, 1)
void gemm_kernel(const float* __restrict__ x) {
    extern __shared__ char smem[];
    const uint32_t sb = smem_u32(smem);
    const int tid = threadIdx.x, lane = tid & 31, wid = tid >> 5;
    const int wm = wid & 3, wn = wid >> 2;            // 4x4 warp grid
    const int mwarp = wm * 32, nwarp = wn * 32;
    const int m0 = blockIdx.y * BM;
    const int n0 = blockIdx.x * BN;
    const int bi = m0 >> 14, mb = m0 & (TH_ - 1);
    const float* xb = x + (size_t)bi * C_ * TH_ + mb;

    // A loader: 512 slots of 8 floats; 1 slot/thread
    const int ka0 = tid >> 4, mo0 = tid & 15;

    // ldmatrix lane offsets
    const int krl = (lane & 7) + ((lane >> 4) & 1) * 8;
    const int mcl = ((lane >> 3) & 1) * 8;
    uint32_t cA[2];
#pragma unroll
    for (int i = 0; i < 2; ++i)
        cA[i] = krl * 256 + (((mwarp + i * 16 + mcl) * 2) ^ ((krl & 7) << 4));
    const int nll = (lane & 7) + ((lane >> 4) & 1) * 8;
    const int kcl = ((lane >> 3) & 1) * 8;
    const uint32_t cB = (nwarp + nll) * WROWB + kcl * 2;

    float acc[2][4][4];
#pragma unroll
    for (int i = 0; i < 2; ++i)
#pragma unroll
        for (int j = 0; j < 4; ++j)
#pragma unroll
            for (int q = 0; q < 4; ++q) acc[i][j][q] = 0.f;

    auto issue_W = [&](int s) {
        const uint32_t wb = sb + (s % 3) * ST_SZ + ST_W_H;
        const int kk = s * BK;
#pragma unroll
        for (int r = 0; r < 2; ++r) {
            int slot = tid + 512 * r;
            int n = (slot >> 2) & 127, kc = slot & 3;
            const __nv_bfloat16* src = (r ? g_Wl : g_Wh) + (size_t)(n0 + n) * C_ + kk + kc * 8;
            cp_async16(wb + r * (ST_W_L - ST_W_H) + n * WROWB + kc * 16, src);
        }
        CP_COMMIT();
    };
    auto ldg_A = [&](int s, float4* f) {
        const float* r0 = xb + (size_t)(s * BK + ka0) * TH_ + mo0 * 8;
        f[0] = *(const float4*)r0;
        f[1] = *(const float4*)(r0 + 4);
    };
    auto sts_A = [&](int s, const float4* f) {
        const uint32_t ab = sb + (s % 3) * ST_SZ;
        uint4 hi, lo;
        split8((const float*)f, hi, lo);
        uint32_t d0 = ab + ka0 * 256 + ((mo0 ^ (ka0 & 7)) << 4);
        sts128(d0 + ST_A_H, hi);
        sts128(d0 + ST_A_L, lo);
    };

    // ---- prologue ----
    {
        float4 f0[2], f1[2];
        ldg_A(0, f0); issue_W(0);
        ldg_A(1, f1); issue_W(1);
        sts_A(0, f0); sts_A(1, f1);
        CP_WAIT(1);                // stage 0 W complete
        __syncthreads();
    }

    // ---- mainloop: single sync per stage ----
    float4 fr[2];
    for (int s = 0; s < NS; ++s) {
        const bool pf = (s + 2 < NS);
        if (pf) { ldg_A(s + 2, fr); issue_W(s + 2); }

        const uint32_t stb = sb + (s % 3) * ST_SZ;
#pragma unroll
        for (int h16 = 0; h16 < 2; ++h16) {
            uint32_t aH[2][4], aL[2][4];
#pragma unroll
            for (int i = 0; i < 2; ++i) {
                ldm_x4_t(aH[i], stb + ST_A_H + h16 * 16 * 256 + cA[i]);
                ldm_x4_t(aL[i], stb + ST_A_L + h16 * 16 * 256 + cA[i]);
            }
#pragma unroll
            for (int j2 = 0; j2 < 2; ++j2) {
                uint32_t bH[4], bL[4];
                ldm_x4(bH, stb + ST_W_H + h16 * 32 + cB + j2 * (16 * WROWB));
                ldm_x4(bL, stb + ST_W_L + h16 * 32 + cB + j2 * (16 * WROWB));
#pragma unroll
                for (int i = 0; i < 2; ++i)
#pragma unroll
                    for (int jj = 0; jj < 2; ++jj) {
                        float* d = acc[i][j2 * 2 + jj];
                        mma16816(d, aH[i], &bH[jj * 2]);
                        mma16816(d, aL[i], &bH[jj * 2]);
                        mma16816(d, aH[i], &bL[jj * 2]);
                    }
            }
        }
        if (pf) sts_A(s + 2, fr);
        if (pf) { CP_WAIT(1); } else { CP_WAIT(0); }
        __syncthreads();
    }

    // ---- store z ----
    const int rbase = m0 + mwarp + (lane >> 2);
    const int cbase = n0 + nwarp + (lane & 3) * 2;
#pragma unroll
    for (int i = 0; i < 2; ++i)
#pragma unroll
        for (int j = 0; j < 4; ++j) {
            float* d = acc[i][j];
            size_t r0 = (size_t)(rbase + i * 16) * OUT_ + cbase + j * 8;
            *(float2*)&g_Z[r0] = make_float2(d[0], d[1]);
            *(float2*)&g_Z[r0 + 8 * OUT_] = make_float2(d[2], d[3]);
        }
}

// ---------------- epilogue ----------------
#define EM 32
#define EZS 516
__global__ __launch_bounds__(256, 2)
void epilogue_kernel(const float* __restrict__ x, const float* __restrict__ prelu2_a,
                     const float* __restrict__ lnw, const float* __restrict__ lnb,
                     float* __restrict__ out) {
    extern __shared__ float zb[];          // [EM][EZS] + mu[EM] + rs[EM]
    float* mu_s = zb + EM * EZS;
    float* rs_s = mu_s + EM;
    const int tid = threadIdx.x, lane = tid & 31, warp = tid >> 5;
    const int m0 = blockIdx.x * EM;
    const int bi = m0 >> 14, mb = m0 & (TH_ - 1);
    const float a2 = *prelu2_a;
    const float* sp = g_sproj + bi * OUT_;

#pragma unroll 4
    for (int r = 0; r < 16; ++r) {
        int idx = tid + 256 * r;
        int m = idx >> 7, q4 = idx & 127;
        float4 v = *(const float4*)&g_Z[(size_t)(m0 + m) * OUT_ + q4 * 4];
        float4 spv = *(const float4*)&sp[q4 * 4];
        v.x += spv.x; v.y += spv.y; v.z += spv.z; v.w += spv.w;
        v.x = (v.x >= 0.f) ? v.x : a2 * v.x;
        v.y = (v.y >= 0.f) ? v.y : a2 * v.y;
        v.z = (v.z >= 0.f) ? v.z : a2 * v.z;
        v.w = (v.w >= 0.f) ? v.w : a2 * v.w;
        *(float4*)&zb[m * EZS + q4 * 4] = v;
    }
    __syncthreads();

    for (int j = warp * 4; j < warp * 4 + 4; ++j) {
        const float* zr = &zb[j * EZS];
        float sum = 0.f, ssq = 0.f;
#pragma unroll
        for (int it = 0; it < 16; ++it) {
            float v = zr[lane + it * 32];
            sum += v; ssq += v * v;
        }
#pragma unroll
        for (int off = 16; off; off >>= 1) {
            sum += __shfl_xor_sync(0xffffffffu, sum, off);
            ssq += __shfl_xor_sync(0xffffffffu, ssq, off);
        }
        if (lane == 0) {
            float mu = sum * (1.f / OUT_);
            mu_s[j] = mu;
            rs_s[j] = rsqrtf(ssq * (1.f / OUT_) - mu * mu + 1e-8f);
        }
    }
    __syncthreads();

    for (int o = tid; o < OUT_; o += 256) {
        const float lw = lnw[o], lb = lnb[o];
        const size_t gbase = ((size_t)(bi * OUT_ + o)) * TH_ + mb;
#pragma unroll 4
        for (int mq = 0; mq < EM; mq += 4) {
            float4 xv = *(const float4*)(x + gbase + mq);
            float4 yv;
            yv.x = xv.x + (zb[(mq + 0) * EZS + o] - mu_s[mq + 0]) * rs_s[mq + 0] * lw + lb;
            yv.y = xv.y + (zb[(mq + 1) * EZS + o] - mu_s[mq + 1]) * rs_s[mq + 1] * lw + lb;
            yv.z = xv.z + (zb[(mq + 2) * EZS + o] - mu_s[mq + 2]) * rs_s[mq + 2] * lw + lb;
            yv.w = xv.w + (zb[(mq + 3) * EZS + o] - mu_s[mq + 3]) * rs_s[mq + 3] * lw + lb;
            *(float4*)(out + gbase + mq) = yv;
        }
    }
}

// ---------------- launch ----------------
extern "C" void kernel_launch(void* const* d_in, const int* in_sizes, int n_in,
                              void* d_out, int out_size) {
    (void)in_sizes; (void)n_in; (void)out_size;
    const float* x        = (const float*)d_in[0];
    const float* s        = (const float*)d_in[1];
    const float* W        = (const float*)d_in[5];
    const float* bias     = (const float*)d_in[6];
    const float* prelu2_a = (const float*)d_in[7];
    const float* ln2_w    = (const float*)d_in[8];
    const float* ln2_b    = (const float*)d_in[9];
    float* out = (float*)d_out;

    cudaFuncSetAttribute(gemm_kernel, cudaFuncAttributeMaxDynamicSharedMemorySize, GEMM_SMEM);
    size_t esm = (size_t)(EM * EZS + 2 * EM) * sizeof(float);
    cudaFuncSetAttribute(epilogue_kernel, cudaFuncAttributeMaxDynamicSharedMemorySize, (int)esm);

    sproj_kernel<<<B_, 256>>>(s, W, bias);
    wprep_kernel<<<OUT_, 256>>>(W);
    dim3 grid(OUT_ / BN, MTOT_ / BM);
    gemm_kernel<<<grid, NTHR, GEMM_SMEM>>>(x);
    epilogue_kernel<<<MTOT_ / EM, 256, esm>>>(x, prelu2_a, ln2_w, ln2_b, out);
}

// round 6
// speedup vs baseline: 2.5160x; 1.1258x over previous
#include <cuda_runtime.h>
#include <cuda_bf16.h>
#include <cstdint>

// ---------------- problem constants ----------------
#define B_     4
#define C_     512
#define TH_    16384
#define MTOT_  (B_ * TH_)
#define KW_    768
#define AUX_   256
#define OUT_   512

// ---------------- tiling ----------------
#define BM 64
#define BK 32
#define NS (C_ / BK)            // 16 stages
#define NTHR 512
// stage layout (bytes): A_hi 4K | A_lo 4K | W_hi 40960 | W_lo 40960
#define ST_A_H  0
#define ST_A_L  4096
#define ST_W_H  8192
#define ST_W_L  49152
#define ST_SZ   90112
#define SMEM_TOTAL (2 * ST_SZ)   // 180224 B
#define WROWB 80

// epilogue smem (floats, overlaid on stage memory)
#define EZS 520
#define ZB_F   (BM * EZS)               // 33280
#define PART_F (ZB_F)                   // part[8][64][2] at 33280
#define MU_F   (PART_F + 1024)          // 34304
#define RS_F   (MU_F + 64)              // 34368

// ---------------- device scratch ----------------
__device__ __align__(16) __nv_bfloat16 g_Wh[(size_t)OUT_ * C_];
__device__ __align__(16) __nv_bfloat16 g_Wl[(size_t)OUT_ * C_];
__device__ float g_sproj[B_ * OUT_];

// ---------------- asm helpers ----------------
__device__ __forceinline__ uint32_t smem_u32(const void* p) {
    uint32_t a;
    asm("{ .reg .u64 t; cvta.to.shared.u64 t, %1; cvt.u32.u64 %0, t; }" : "=r"(a) : "l"(p));
    return a;
}
__device__ __forceinline__ void cp_async16(uint32_t dst, const void* src) {
    asm volatile("cp.async.cg.shared.global [%0], [%1], 16;" :: "r"(dst), "l"(src) : "memory");
}
#define CP_COMMIT() asm volatile("cp.async.commit_group;" ::: "memory")
#define CP_WAIT(n)  asm volatile("cp.async.wait_group %0;" :: "n"(n) : "memory")

__device__ __forceinline__ void ldm_x4(uint32_t* r, uint32_t addr) {
    asm volatile("ldmatrix.sync.aligned.m8n8.x4.shared.b16 {%0,%1,%2,%3}, [%4];"
                 : "=r"(r[0]), "=r"(r[1]), "=r"(r[2]), "=r"(r[3]) : "r"(addr));
}
__device__ __forceinline__ void ldm_x4_t(uint32_t* r, uint32_t addr) {
    asm volatile("ldmatrix.sync.aligned.m8n8.x4.trans.shared.b16 {%0,%1,%2,%3}, [%4];"
                 : "=r"(r[0]), "=r"(r[1]), "=r"(r[2]), "=r"(r[3]) : "r"(addr));
}
__device__ __forceinline__ void mma16816(float* d, const uint32_t* a, const uint32_t* b) {
    asm volatile(
        "mma.sync.aligned.m16n8k16.row.col.f32.bf16.bf16.f32 "
        "{%0,%1,%2,%3},{%4,%5,%6,%7},{%8,%9},{%0,%1,%2,%3};"
        : "+f"(d[0]), "+f"(d[1]), "+f"(d[2]), "+f"(d[3])
        : "r"(a[0]), "r"(a[1]), "r"(a[2]), "r"(a[3]), "r"(b[0]), "r"(b[1]));
}
__device__ __forceinline__ void sts64(uint32_t dst, uint32_t a, uint32_t b) {
    asm volatile("st.shared.v2.b32 [%0], {%1,%2};" :: "r"(dst), "r"(a), "r"(b) : "memory");
}

// split 4 floats -> bf16 hi pair-packed (2 u32) and lo (2 u32)
__device__ __forceinline__ void split4(const float* f, uint32_t* hi, uint32_t* lo) {
    unsigned short h[4], l[4];
#pragma unroll
    for (int j = 0; j < 4; ++j) {
        __nv_bfloat16 hb = __float2bfloat16_rn(f[j]);
        __nv_bfloat16 lb = __float2bfloat16_rn(f[j] - __bfloat162float(hb));
        h[j] = __bfloat16_as_ushort(hb);
        l[j] = __bfloat16_as_ushort(lb);
    }
    hi[0] = (uint32_t)h[0] | ((uint32_t)h[1] << 16);
    hi[1] = (uint32_t)h[2] | ((uint32_t)h[3] << 16);
    lo[0] = (uint32_t)l[0] | ((uint32_t)l[1] << 16);
    lo[1] = (uint32_t)l[2] | ((uint32_t)l[3] << 16);
}

// ---------------- prep kernels ----------------
__global__ void sproj_kernel(const float* __restrict__ s, const float* __restrict__ W,
                             const float* __restrict__ bias) {
    __shared__ float ss[AUX_];
    int b = blockIdx.x, tid = threadIdx.x;
    if (tid < AUX_) ss[tid] = s[b * AUX_ + tid];
    __syncthreads();
    for (int o = tid; o < OUT_; o += blockDim.x) {
        const float* wr = W + (size_t)o * KW_ + C_;
        float acc = bias[o];
#pragma unroll 8
        for (int k = 0; k < AUX_; ++k) acc += ss[k] * wr[k];
        g_sproj[b * OUT_ + o] = acc;
    }
}

__global__ void wprep_kernel(const float* __restrict__ W) {
    int n = blockIdx.x, t = threadIdx.x;
#pragma unroll
    for (int r = 0; r < 2; ++r) {
        int k = t + r * 256;
        float f = W[(size_t)n * KW_ + k];
        __nv_bfloat16 hb = __float2bfloat16_rn(f);
        __nv_bfloat16 lb = __float2bfloat16_rn(f - __bfloat162float(hb));
        g_Wh[(size_t)n * C_ + k] = hb;
        g_Wl[(size_t)n * C_ + k] = lb;
    }
}

// ---------------- fused GEMM + PReLU + LN + residual ----------------
__global__ __launch_bounds__(NTHR, 1)
void fused_kernel(const float* __restrict__ x, const float* __restrict__ prelu2_a,
                  const float* __restrict__ lnw, const float* __restrict__ lnb,
                  float* __restrict__ out) {
    extern __shared__ char smem[];
    const uint32_t sb = smem_u32(smem);
    float* smf = (float*)smem;

    const int tid = threadIdx.x, lane = tid & 31, wid = tid >> 5;
    const int wm = wid & 1, wn = wid >> 1;        // 2 x 8 warp grid
    const int mwarp = wm * 32, nwarp = wn * 64;
    const int m0 = blockIdx.x * BM;
    const int bi = m0 >> 14, mb = m0 & (TH_ - 1);
    const float* xb = x + (size_t)bi * C_ * TH_ + mb;

    // A loader: thread -> (k = tid>>4, 4 tokens at mo4*4)
    const int ka = tid >> 4, mo4 = tid & 15;
    const uint32_t a_sts_off = ka * 128 + (((mo4 >> 1) ^ (ka & 7)) << 4) + (mo4 & 1) * 8;
    const float* a_src = xb + (size_t)ka * TH_ + mo4 * 4;

    // ldmatrix lane offsets
    const int krl = (lane & 7) + ((lane >> 4) & 1) * 8;
    const int mcl = ((lane >> 3) & 1) * 8;
    uint32_t cA[2];
#pragma unroll
    for (int i = 0; i < 2; ++i)
        cA[i] = krl * 128 + ((((mwarp + i * 16 + mcl) >> 3) ^ (krl & 7)) << 4);
    const int nll = (lane & 7) + ((lane >> 4) & 1) * 8;
    const int kcl = ((lane >> 3) & 1) * 8;
    const uint32_t cB = (nwarp + nll) * WROWB + kcl * 2;

    float acc[2][8][4];
#pragma unroll
    for (int i = 0; i < 2; ++i)
#pragma unroll
        for (int j = 0; j < 8; ++j)
#pragma unroll
            for (int q = 0; q < 4; ++q) acc[i][j][q] = 0.f;

    auto issue_W = [&](int s) {
        const uint32_t wb = sb + (s & 1) * ST_SZ + ST_W_H;
        const int kk = s * BK;
#pragma unroll
        for (int r = 0; r < 8; ++r) {
            const int hl = r >> 2;                       // 0: hi, 1: lo
            const int n = (r & 3) * 128 + (tid >> 2);
            const int kc = tid & 3;
            const __nv_bfloat16* src = (hl ? g_Wl : g_Wh) + (size_t)n * C_ + kk + kc * 8;
            cp_async16(wb + hl * (ST_W_L - ST_W_H) + n * WROWB + kc * 16, src);
        }
        CP_COMMIT();
    };
    auto ldg_A = [&](int s, float4& f) {
        f = *(const float4*)(a_src + (size_t)s * BK * TH_);
    };
    auto sts_A = [&](int s, const float4& f) {
        const uint32_t ab = sb + (s & 1) * ST_SZ;
        uint32_t hi[2], lo[2];
        split4((const float*)&f, hi, lo);
        sts64(ab + ST_A_H + a_sts_off, hi[0], hi[1]);
        sts64(ab + ST_A_L + a_sts_off, lo[0], lo[1]);
    };

    // ---- prologue ----
    {
        float4 f0;
        ldg_A(0, f0);
        issue_W(0);
        sts_A(0, f0);
        CP_WAIT(0);
        __syncthreads();
    }

    // ---- mainloop ----
    for (int s = 0; s < NS; ++s) {
        const bool pf = (s + 1 < NS);
        float4 fr;
        if (pf) { issue_W(s + 1); ldg_A(s + 1, fr); }

        const uint32_t stb = sb + (s & 1) * ST_SZ;
#pragma unroll
        for (int h16 = 0; h16 < 2; ++h16) {
            uint32_t aH[2][4], aL[2][4];
#pragma unroll
            for (int i = 0; i < 2; ++i) {
                ldm_x4_t(aH[i], stb + ST_A_H + h16 * 2048 + cA[i]);
                ldm_x4_t(aL[i], stb + ST_A_L + h16 * 2048 + cA[i]);
            }
#pragma unroll
            for (int j2 = 0; j2 < 4; ++j2) {
                uint32_t bH[4], bL[4];
                ldm_x4(bH, stb + ST_W_H + cB + j2 * (16 * WROWB) + h16 * 32);
                ldm_x4(bL, stb + ST_W_L + cB + j2 * (16 * WROWB) + h16 * 32);
#pragma unroll
                for (int i = 0; i < 2; ++i)
#pragma unroll
                    for (int jj = 0; jj < 2; ++jj) {
                        float* d = acc[i][j2 * 2 + jj];
                        mma16816(d, aH[i], &bH[jj * 2]);
                        mma16816(d, aL[i], &bH[jj * 2]);
                        mma16816(d, aH[i], &bL[jj * 2]);
                    }
            }
        }
        if (pf) {
            sts_A(s + 1, fr);
            CP_WAIT(0);
        }
        __syncthreads();
    }

    // ---- in-kernel epilogue ----
    const float a2 = *prelu2_a;
    // sproj for my 16 columns
    float2 spv[8];
#pragma unroll
    for (int j = 0; j < 8; ++j)
        spv[j] = *(const float2*)&g_sproj[bi * OUT_ + nwarp + j * 8 + (lane & 3) * 2];

    // PReLU (in place) + per-thread partial stats for 4 token rows
    float su[4] = {0.f, 0.f, 0.f, 0.f}, sq[4] = {0.f, 0.f, 0.f, 0.f};
#pragma unroll
    for (int i = 0; i < 2; ++i)
#pragma unroll
        for (int j = 0; j < 8; ++j)
#pragma unroll
            for (int q = 0; q < 4; ++q) {
                float v = acc[i][j][q] + ((q & 1) ? spv[j].y : spv[j].x);
                v = (v >= 0.f) ? v : a2 * v;
                acc[i][j][q] = v;
                const int si = i * 2 + (q >> 1);
                su[si] += v; sq[si] += v * v;
            }
    // quad reduce (4 threads share a token row)
#pragma unroll
    for (int si = 0; si < 4; ++si) {
#pragma unroll
        for (int off = 1; off <= 2; off <<= 1) {
            su[si] += __shfl_xor_sync(0xffffffffu, su[si], off);
            sq[si] += __shfl_xor_sync(0xffffffffu, sq[si], off);
        }
    }
    if ((lane & 3) == 0) {
#pragma unroll
        for (int si = 0; si < 4; ++si) {
            const int tok = mwarp + (si >> 1) * 16 + (si & 1) * 8 + (lane >> 2);
            smf[PART_F + wn * 128 + tok * 2] = su[si];
            smf[PART_F + wn * 128 + tok * 2 + 1] = sq[si];
        }
    }
    // stage z into zb (post-PReLU values)
#pragma unroll
    for (int i = 0; i < 2; ++i) {
        const int tok = mwarp + i * 16 + (lane >> 2);
#pragma unroll
        for (int j = 0; j < 8; ++j) {
            const int c = nwarp + j * 8 + (lane & 3) * 2;
            *(float2*)&smf[tok * EZS + c] = make_float2(acc[i][j][0], acc[i][j][1]);
            *(float2*)&smf[(tok + 8) * EZS + c] = make_float2(acc[i][j][2], acc[i][j][3]);
        }
    }
    __syncthreads();

    if (tid < 64) {
        float s0 = 0.f, s1 = 0.f;
#pragma unroll
        for (int w = 0; w < 8; ++w) {
            s0 += smf[PART_F + w * 128 + tid * 2];
            s1 += smf[PART_F + w * 128 + tid * 2 + 1];
        }
        const float mu = s0 * (1.f / 512.f);
        smf[MU_F + tid] = mu;
        smf[RS_F + tid] = rsqrtf(s1 * (1.f / 512.f) - mu * mu + 1e-8f);
    }
    __syncthreads();

    // coalesced transposed write: thread = one channel o, 64 tokens
    {
        const int o = tid;
        const float lw = lnw[o], lb = lnb[o];
        const size_t gbase = ((size_t)(bi * OUT_ + o)) * TH_ + mb;
#pragma unroll 4
        for (int mq = 0; mq < BM; mq += 4) {
            float4 xv = *(const float4*)(x + gbase + mq);
            float4 yv;
            yv.x = xv.x + (smf[(mq + 0) * EZS + o] - smf[MU_F + mq + 0]) * smf[RS_F + mq + 0] * lw + lb;
            yv.y = xv.y + (smf[(mq + 1) * EZS + o] - smf[MU_F + mq + 1]) * smf[RS_F + mq + 1] * lw + lb;
            yv.z = xv.z + (smf[(mq + 2) * EZS + o] - smf[MU_F + mq + 2]) * smf[RS_F + mq + 2] * lw + lb;
            yv.w = xv.w + (smf[(mq + 3) * EZS + o] - smf[MU_F + mq + 3]) * smf[RS_F + mq + 3] * lw + lb;
            *(float4*)(out + gbase + mq) = yv;
        }
    }
}

// ---------------- launch ----------------
extern "C" void kernel_launch(void* const* d_in, const int* in_sizes, int n_in,
                              void* d_out, int out_size) {
    (void)in_sizes; (void)n_in; (void)out_size;
    const float* x        = (const float*)d_in[0];
    const float* s        = (const float*)d_in[1];
    const float* W        = (const float*)d_in[5];
    const float* bias     = (const float*)d_in[6];
    const float* prelu2_a = (const float*)d_in[7];
    const float* ln2_w    = (const float*)d_in[8];
    const float* ln2_b    = (const float*)d_in[9];
    float* out = (float*)d_out;

    cudaFuncSetAttribute(fused_kernel, cudaFuncAttributeMaxDynamicSharedMemorySize, SMEM_TOTAL);

    sproj_kernel<<<B_, 256>>>(s, W, bias);
    wprep_kernel<<<OUT_, 256>>>(W);
    fused_kernel<<<MTOT_ / BM, NTHR, SMEM_TOTAL>>>(x, prelu2_a, ln2_w, ln2_b, out);
}

// round 7
// speedup vs baseline: 4.1301x; 1.6415x over previous
#include <cuda_runtime.h>
#include <cuda_fp16.h>
#include <cstdint>

// ---------------- problem constants ----------------
#define B_     4
#define C_     512
#define TH_    16384
#define MTOT_  (B_ * TH_)
#define KW_    768
#define AUX_   256
#define OUT_   512

// ---------------- tiling ----------------
#define BM 64
#define BK 32
#define NS (C_ / BK)            // 16 stages
#define NTHR 512
// stage layout (bytes): A_hi 4K | A_lo 4K | W 40960
#define ST_A_H  0
#define ST_A_L  4096
#define ST_W    8192
#define ST_SZ   49152
#define WROWB 80

// epilogue smem (floats, overlaid on stage memory)
#define EZS 520
#define ZB_F   (BM * EZS)               // 33280
#define PART_F (ZB_F)                   // part[8][64][2]
#define MU_F   (PART_F + 1024)
#define RS_F   (MU_F + 64)
#define SMEM_TOTAL 137728               // max(2*ST_SZ, epilogue bytes)

// ---------------- device scratch ----------------
__device__ __align__(16) __half g_Wh[(size_t)OUT_ * C_];
__device__ float g_sproj[B_ * OUT_];

// ---------------- asm helpers ----------------
__device__ __forceinline__ uint32_t smem_u32(const void* p) {
    uint32_t a;
    asm("{ .reg .u64 t; cvta.to.shared.u64 t, %1; cvt.u32.u64 %0, t; }" : "=r"(a) : "l"(p));
    return a;
}
__device__ __forceinline__ void cp_async16(uint32_t dst, const void* src) {
    asm volatile("cp.async.cg.shared.global [%0], [%1], 16;" :: "r"(dst), "l"(src) : "memory");
}
#define CP_COMMIT() asm volatile("cp.async.commit_group;" ::: "memory")
#define CP_WAIT(n)  asm volatile("cp.async.wait_group %0;" :: "n"(n) : "memory")

__device__ __forceinline__ void ldm_x4(uint32_t* r, uint32_t addr) {
    asm volatile("ldmatrix.sync.aligned.m8n8.x4.shared.b16 {%0,%1,%2,%3}, [%4];"
                 : "=r"(r[0]), "=r"(r[1]), "=r"(r[2]), "=r"(r[3]) : "r"(addr));
}
__device__ __forceinline__ void ldm_x4_t(uint32_t* r, uint32_t addr) {
    asm volatile("ldmatrix.sync.aligned.m8n8.x4.trans.shared.b16 {%0,%1,%2,%3}, [%4];"
                 : "=r"(r[0]), "=r"(r[1]), "=r"(r[2]), "=r"(r[3]) : "r"(addr));
}
__device__ __forceinline__ void mma16816(float* d, const uint32_t* a, const uint32_t* b) {
    asm volatile(
        "mma.sync.aligned.m16n8k16.row.col.f32.f16.f16.f32 "
        "{%0,%1,%2,%3},{%4,%5,%6,%7},{%8,%9},{%0,%1,%2,%3};"
        : "+f"(d[0]), "+f"(d[1]), "+f"(d[2]), "+f"(d[3])
        : "r"(a[0]), "r"(a[1]), "r"(a[2]), "r"(a[3]), "r"(b[0]), "r"(b[1]));
}
__device__ __forceinline__ void sts64(uint32_t dst, uint32_t a, uint32_t b) {
    asm volatile("st.shared.v2.b32 [%0], {%1,%2};" :: "r"(dst), "r"(a), "r"(b) : "memory");
}

// split 4 floats -> fp16 hi (2 u32) and fp16 lo (2 u32)
__device__ __forceinline__ void split4h(const float* f, uint32_t* hi, uint32_t* lo) {
    unsigned short h[4], l[4];
#pragma unroll
    for (int j = 0; j < 4; ++j) {
        __half hb = __float2half_rn(f[j]);
        __half lb = __float2half_rn(f[j] - __half2float(hb));
        h[j] = __half_as_ushort(hb);
        l[j] = __half_as_ushort(lb);
    }
    hi[0] = (uint32_t)h[0] | ((uint32_t)h[1] << 16);
    hi[1] = (uint32_t)h[2] | ((uint32_t)h[3] << 16);
    lo[0] = (uint32_t)l[0] | ((uint32_t)l[1] << 16);
    lo[1] = (uint32_t)l[2] | ((uint32_t)l[3] << 16);
}

// ---------------- prep kernels ----------------
// grid (B_, OUT_/64), block 256: 8 warps x 8 outputs, warp-reduce over AUX
__global__ void sproj_kernel(const float* __restrict__ s, const float* __restrict__ W,
                             const float* __restrict__ bias) {
    __shared__ float ss[AUX_];
    const int b = blockIdx.x, o0 = blockIdx.y * 64;
    const int tid = threadIdx.x, lane = tid & 31, warp = tid >> 5;
    if (tid < AUX_) ss[tid] = s[b * AUX_ + tid];
    __syncthreads();
    float sl[8];
    *(float4*)&sl[0] = *(const float4*)&ss[lane * 8];
    *(float4*)&sl[4] = *(const float4*)&ss[lane * 8 + 4];
#pragma unroll
    for (int i = 0; i < 8; ++i) {
        const int o = o0 + warp * 8 + i;
        const float* wr = W + (size_t)o * KW_ + C_ + lane * 8;
        float4 w0 = *(const float4*)wr;
        float4 w1 = *(const float4*)(wr + 4);
        float acc = sl[0] * w0.x + sl[1] * w0.y + sl[2] * w0.z + sl[3] * w0.w +
                    sl[4] * w1.x + sl[5] * w1.y + sl[6] * w1.z + sl[7] * w1.w;
#pragma unroll
        for (int off = 16; off; off >>= 1) acc += __shfl_xor_sync(0xffffffffu, acc, off);
        if (lane == 0) g_sproj[b * OUT_ + o] = acc + bias[o];
    }
}

__global__ void wprep_kernel(const float* __restrict__ W) {
    int n = blockIdx.x, t = threadIdx.x;
#pragma unroll
    for (int r = 0; r < 2; ++r) {
        int k = t + r * 256;
        g_Wh[(size_t)n * C_ + k] = __float2half_rn(W[(size_t)n * KW_ + k]);
    }
}

// ---------------- fused GEMM + PReLU + LN + residual ----------------
__global__ __launch_bounds__(NTHR, 1)
void fused_kernel(const float* __restrict__ x, const float* __restrict__ prelu2_a,
                  const float* __restrict__ lnw, const float* __restrict__ lnb,
                  float* __restrict__ out) {
    extern __shared__ char smem[];
    const uint32_t sb = smem_u32(smem);
    float* smf = (float*)smem;

    const int tid = threadIdx.x, lane = tid & 31, wid = tid >> 5;
    const int wm = wid & 1, wn = wid >> 1;        // 2 x 8 warp grid
    const int mwarp = wm * 32, nwarp = wn * 64;
    const int m0 = blockIdx.x * BM;
    const int bi = m0 >> 14, mb = m0 & (TH_ - 1);
    const float* xb = x + (size_t)bi * C_ * TH_ + mb;

    // A loader: thread -> (k = tid>>4, 4 tokens at mo4*4)
    const int ka = tid >> 4, mo4 = tid & 15;
    const uint32_t a_sts_off = ka * 128 + (((mo4 >> 1) ^ (ka & 7)) << 4) + (mo4 & 1) * 8;
    const float* a_src = xb + (size_t)ka * TH_ + mo4 * 4;

    // ldmatrix lane offsets
    const int krl = (lane & 7) + ((lane >> 4) & 1) * 8;
    const int mcl = ((lane >> 3) & 1) * 8;
    uint32_t cA[2];
#pragma unroll
    for (int i = 0; i < 2; ++i)
        cA[i] = krl * 128 + ((((mwarp + i * 16 + mcl) >> 3) ^ (krl & 7)) << 4);
    const int nll = (lane & 7) + ((lane >> 4) & 1) * 8;
    const int kcl = ((lane >> 3) & 1) * 8;
    const uint32_t cB = (nwarp + nll) * WROWB + kcl * 2;

    float acc[2][8][4];
#pragma unroll
    for (int i = 0; i < 2; ++i)
#pragma unroll
        for (int j = 0; j < 8; ++j)
#pragma unroll
            for (int q = 0; q < 4; ++q) acc[i][j][q] = 0.f;

    auto issue_W = [&](int s) {
        const uint32_t wb = sb + (s & 1) * ST_SZ + ST_W;
        const int kk = s * BK;
#pragma unroll
        for (int r = 0; r < 4; ++r) {
            const int n = r * 128 + (tid >> 2);
            const int kc = tid & 3;
            cp_async16(wb + n * WROWB + kc * 16, g_Wh + (size_t)n * C_ + kk + kc * 8);
        }
        CP_COMMIT();
    };
    auto ldg_A = [&](int s, float4& f) {
        f = *(const float4*)(a_src + (size_t)s * BK * TH_);
    };
    auto sts_A = [&](int s, const float4& f) {
        const uint32_t ab = sb + (s & 1) * ST_SZ;
        uint32_t hi[2], lo[2];
        split4h((const float*)&f, hi, lo);
        sts64(ab + ST_A_H + a_sts_off, hi[0], hi[1]);
        sts64(ab + ST_A_L + a_sts_off, lo[0], lo[1]);
    };

    // ---- prologue ----
    {
        float4 f0;
        ldg_A(0, f0);
        issue_W(0);
        sts_A(0, f0);
        CP_WAIT(0);
        __syncthreads();
    }

    // ---- mainloop ----
    for (int s = 0; s < NS; ++s) {
        const bool pf = (s + 1 < NS);
        float4 fr;
        if (pf) { issue_W(s + 1); ldg_A(s + 1, fr); }

        const uint32_t stb = sb + (s & 1) * ST_SZ;
#pragma unroll
        for (int h16 = 0; h16 < 2; ++h16) {
            uint32_t aH[2][4], aL[2][4];
#pragma unroll
            for (int i = 0; i < 2; ++i) {
                ldm_x4_t(aH[i], stb + ST_A_H + h16 * 2048 + cA[i]);
                ldm_x4_t(aL[i], stb + ST_A_L + h16 * 2048 + cA[i]);
            }
#pragma unroll
            for (int j2 = 0; j2 < 4; ++j2) {
                uint32_t bH[4];
                ldm_x4(bH, stb + ST_W + cB + j2 * (16 * WROWB) + h16 * 32);
#pragma unroll
                for (int i = 0; i < 2; ++i)
#pragma unroll
                    for (int jj = 0; jj < 2; ++jj) {
                        float* d = acc[i][j2 * 2 + jj];
                        mma16816(d, aH[i], &bH[jj * 2]);
                        mma16816(d, aL[i], &bH[jj * 2]);
                    }
            }
        }
        if (pf) {
            sts_A(s + 1, fr);
            CP_WAIT(0);
        }
        __syncthreads();
    }

    // ---- in-kernel epilogue ----
    const float a2 = *prelu2_a;
    float2 spv[8];
#pragma unroll
    for (int j = 0; j < 8; ++j)
        spv[j] = *(const float2*)&g_sproj[bi * OUT_ + nwarp + j * 8 + (lane & 3) * 2];

    float su[4] = {0.f, 0.f, 0.f, 0.f}, sq[4] = {0.f, 0.f, 0.f, 0.f};
#pragma unroll
    for (int i = 0; i < 2; ++i)
#pragma unroll
        for (int j = 0; j < 8; ++j)
#pragma unroll
            for (int q = 0; q < 4; ++q) {
                float v = acc[i][j][q] + ((q & 1) ? spv[j].y : spv[j].x);
                v = (v >= 0.f) ? v : a2 * v;
                acc[i][j][q] = v;
                const int si = i * 2 + (q >> 1);
                su[si] += v; sq[si] += v * v;
            }
#pragma unroll
    for (int si = 0; si < 4; ++si) {
#pragma unroll
        for (int off = 1; off <= 2; off <<= 1) {
            su[si] += __shfl_xor_sync(0xffffffffu, su[si], off);
            sq[si] += __shfl_xor_sync(0xffffffffu, sq[si], off);
        }
    }
    if ((lane & 3) == 0) {
#pragma unroll
        for (int si = 0; si < 4; ++si) {
            const int tok = mwarp + (si >> 1) * 16 + (si & 1) * 8 + (lane >> 2);
            smf[PART_F + wn * 128 + tok * 2] = su[si];
            smf[PART_F + wn * 128 + tok * 2 + 1] = sq[si];
        }
    }
#pragma unroll
    for (int i = 0; i < 2; ++i) {
        const int tok = mwarp + i * 16 + (lane >> 2);
#pragma unroll
        for (int j = 0; j < 8; ++j) {
            const int c = nwarp + j * 8 + (lane & 3) * 2;
            *(float2*)&smf[tok * EZS + c] = make_float2(acc[i][j][0], acc[i][j][1]);
            *(float2*)&smf[(tok + 8) * EZS + c] = make_float2(acc[i][j][2], acc[i][j][3]);
        }
    }
    __syncthreads();

    if (tid < 64) {
        float s0 = 0.f, s1 = 0.f;
#pragma unroll
        for (int w = 0; w < 8; ++w) {
            s0 += smf[PART_F + w * 128 + tid * 2];
            s1 += smf[PART_F + w * 128 + tid * 2 + 1];
        }
        const float mu = s0 * (1.f / 512.f);
        smf[MU_F + tid] = mu;
        smf[RS_F + tid] = rsqrtf(s1 * (1.f / 512.f) - mu * mu + 1e-8f);
    }
    __syncthreads();

    {
        const int o = tid;
        const float lw = lnw[o], lb = lnb[o];
        const size_t gbase = ((size_t)(bi * OUT_ + o)) * TH_ + mb;
#pragma unroll 4
        for (int mq = 0; mq < BM; mq += 4) {
            float4 xv = *(const float4*)(x + gbase + mq);
            float4 yv;
            yv.x = xv.x + (smf[(mq + 0) * EZS + o] - smf[MU_F + mq + 0]) * smf[RS_F + mq + 0] * lw + lb;
            yv.y = xv.y + (smf[(mq + 1) * EZS + o] - smf[MU_F + mq + 1]) * smf[RS_F + mq + 1] * lw + lb;
            yv.z = xv.z + (smf[(mq + 2) * EZS + o] - smf[MU_F + mq + 2]) * smf[RS_F + mq + 2] * lw + lb;
            yv.w = xv.w + (smf[(mq + 3) * EZS + o] - smf[MU_F + mq + 3]) * smf[RS_F + mq + 3] * lw + lb;
            *(float4*)(out + gbase + mq) = yv;
        }
    }
}

// ---------------- launch ----------------
extern "C" void kernel_launch(void* const* d_in, const int* in_sizes, int n_in,
                              void* d_out, int out_size) {
    (void)in_sizes; (void)n_in; (void)out_size;
    const float* x        = (const float*)d_in[0];
    const float* s        = (const float*)d_in[1];
    const float* W        = (const float*)d_in[5];
    const float* bias     = (const float*)d_in[6];
    const float* prelu2_a = (const float*)d_in[7];
    const float* ln2_w    = (const float*)d_in[8];
    const float* ln2_b    = (const float*)d_in[9];
    float* out = (float*)d_out;

    cudaFuncSetAttribute(fused_kernel, cudaFuncAttributeMaxDynamicSharedMemorySize, SMEM_TOTAL);

    sproj_kernel<<<dim3(B_, OUT_ / 64), 256>>>(s, W, bias);
    wprep_kernel<<<OUT_, 256>>>(W);
    fused_kernel<<<MTOT_ / BM, NTHR, SMEM_TOTAL>>>(x, prelu2_a, ln2_w, ln2_b, out);
}

// round 8
// speedup vs baseline: 4.1480x; 1.0044x over previous
#include <cuda_runtime.h>
#include <cuda_fp16.h>
#include <cstdint>

// ---------------- problem constants ----------------
#define B_     4
#define C_     512
#define TH_    16384
#define MTOT_  (B_ * TH_)
#define KW_    768
#define AUX_   256
#define OUT_   512

// ---------------- tiling ----------------
#define BM 64
#define BK 32
#define NS (C_ / BK)            // 16 stages
#define NTHR 512
// stage layout (bytes): A_hi 4K | A_lo 4K | W 40960
#define ST_A_H  0
#define ST_A_L  4096
#define ST_W    8192
#define ST_SZ   49152
#define WROWB 80

// epilogue smem (floats, overlaid on stage memory)
#define EZS 520
#define ZB_F   (BM * EZS)               // 33280
#define PART_F (ZB_F)                   // part[8][64][2]
#define MU_F   (PART_F + 1024)
#define RS_F   (MU_F + 64)
#define SMEM_TOTAL 137728               // max(2*ST_SZ, epilogue bytes)

// ---------------- device scratch ----------------
__device__ __align__(16) __half g_Wh[(size_t)OUT_ * C_];
__device__ float g_sproj[B_ * OUT_];

// ---------------- asm helpers ----------------
__device__ __forceinline__ uint32_t smem_u32(const void* p) {
    uint32_t a;
    asm("{ .reg .u64 t; cvta.to.shared.u64 t, %1; cvt.u32.u64 %0, t; }" : "=r"(a) : "l"(p));
    return a;
}
__device__ __forceinline__ void cp_async16(uint32_t dst, const void* src) {
    asm volatile("cp.async.cg.shared.global [%0], [%1], 16;" :: "r"(dst), "l"(src) : "memory");
}
#define CP_COMMIT() asm volatile("cp.async.commit_group;" ::: "memory")
#define CP_WAIT(n)  asm volatile("cp.async.wait_group %0;" :: "n"(n) : "memory")

__device__ __forceinline__ void ldm_x4(uint32_t* r, uint32_t addr) {
    asm volatile("ldmatrix.sync.aligned.m8n8.x4.shared.b16 {%0,%1,%2,%3}, [%4];"
                 : "=r"(r[0]), "=r"(r[1]), "=r"(r[2]), "=r"(r[3]) : "r"(addr));
}
__device__ __forceinline__ void ldm_x4_t(uint32_t* r, uint32_t addr) {
    asm volatile("ldmatrix.sync.aligned.m8n8.x4.trans.shared.b16 {%0,%1,%2,%3}, [%4];"
                 : "=r"(r[0]), "=r"(r[1]), "=r"(r[2]), "=r"(r[3]) : "r"(addr));
}
__device__ __forceinline__ void mma16816(float* d, const uint32_t* a, const uint32_t* b) {
    asm volatile(
        "mma.sync.aligned.m16n8k16.row.col.f32.f16.f16.f32 "
        "{%0,%1,%2,%3},{%4,%5,%6,%7},{%8,%9},{%0,%1,%2,%3};"
        : "+f"(d[0]), "+f"(d[1]), "+f"(d[2]), "+f"(d[3])
        : "r"(a[0]), "r"(a[1]), "r"(a[2]), "r"(a[3]), "r"(b[0]), "r"(b[1]));
}
__device__ __forceinline__ void sts64(uint32_t dst, uint32_t a, uint32_t b) {
    asm volatile("st.shared.v2.b32 [%0], {%1,%2};" :: "r"(dst), "r"(a), "r"(b) : "memory");
}

// split 4 floats -> fp16 hi (2 u32) and fp16 lo (2 u32)
__device__ __forceinline__ void split4h(const float* f, uint32_t* hi, uint32_t* lo) {
    unsigned short h[4], l[4];
#pragma unroll
    for (int j = 0; j < 4; ++j) {
        __half hb = __float2half_rn(f[j]);
        __half lb = __float2half_rn(f[j] - __half2float(hb));
        h[j] = __half_as_ushort(hb);
        l[j] = __half_as_ushort(lb);
    }
    hi[0] = (uint32_t)h[0] | ((uint32_t)h[1] << 16);
    hi[1] = (uint32_t)h[2] | ((uint32_t)h[3] << 16);
    lo[0] = (uint32_t)l[0] | ((uint32_t)l[1] << 16);
    lo[1] = (uint32_t)l[2] | ((uint32_t)l[3] << 16);
}

// ---------------- prep kernels ----------------
// grid (B_, OUT_/64), block 256: 8 warps x 8 outputs, warp-reduce over AUX
__global__ void sproj_kernel(const float* __restrict__ s, const float* __restrict__ W,
                             const float* __restrict__ bias) {
    __shared__ float ss[AUX_];
    const int b = blockIdx.x, o0 = blockIdx.y * 64;
    const int tid = threadIdx.x, lane = tid & 31, warp = tid >> 5;
    if (tid < AUX_) ss[tid] = s[b * AUX_ + tid];
    __syncthreads();
    float sl[8];
    *(float4*)&sl[0] = *(const float4*)&ss[lane * 8];
    *(float4*)&sl[4] = *(const float4*)&ss[lane * 8 + 4];
#pragma unroll
    for (int i = 0; i < 8; ++i) {
        const int o = o0 + warp * 8 + i;
        const float* wr = W + (size_t)o * KW_ + C_ + lane * 8;
        float4 w0 = *(const float4*)wr;
        float4 w1 = *(const float4*)(wr + 4);
        float acc = sl[0] * w0.x + sl[1] * w0.y + sl[2] * w0.z + sl[3] * w0.w +
                    sl[4] * w1.x + sl[5] * w1.y + sl[6] * w1.z + sl[7] * w1.w;
#pragma unroll
        for (int off = 16; off; off >>= 1) acc += __shfl_xor_sync(0xffffffffu, acc, off);
        if (lane == 0) g_sproj[b * OUT_ + o] = acc + bias[o];
    }
}

__global__ void wprep_kernel(const float* __restrict__ W) {
    int n = blockIdx.x, t = threadIdx.x;
#pragma unroll
    for (int r = 0; r < 2; ++r) {
        int k = t + r * 256;
        g_Wh[(size_t)n * C_ + k] = __float2half_rn(W[(size_t)n * KW_ + k]);
    }
}

// ---------------- fused GEMM + PReLU + LN + residual ----------------
__global__ __launch_bounds__(NTHR, 1)
void fused_kernel(const float* __restrict__ x, const float* __restrict__ prelu2_a,
                  const float* __restrict__ lnw, const float* __restrict__ lnb,
                  float* __restrict__ out) {
    extern __shared__ char smem[];
    const uint32_t sb = smem_u32(smem);
    float* smf = (float*)smem;

    const int tid = threadIdx.x, lane = tid & 31, wid = tid >> 5;
    const int wm = wid & 1, wn = wid >> 1;        // 2 x 8 warp grid
    const int mwarp = wm * 32, nwarp = wn * 64;
    const int m0 = blockIdx.x * BM;
    const int bi = m0 >> 14, mb = m0 & (TH_ - 1);
    const float* xb = x + (size_t)bi * C_ * TH_ + mb;

    // A loader: thread -> (k = tid>>4, 4 tokens at mo4*4)
    const int ka = tid >> 4, mo4 = tid & 15;
    const uint32_t a_sts_off = ka * 128 + (((mo4 >> 1) ^ (ka & 7)) << 4) + (mo4 & 1) * 8;
    const float* a_src = xb + (size_t)ka * TH_ + mo4 * 4;

    // ldmatrix lane offsets
    const int krl = (lane & 7) + ((lane >> 4) & 1) * 8;
    const int mcl = ((lane >> 3) & 1) * 8;
    uint32_t cA[2];
#pragma unroll
    for (int i = 0; i < 2; ++i)
        cA[i] = krl * 128 + ((((mwarp + i * 16 + mcl) >> 3) ^ (krl & 7)) << 4);
    const int nll = (lane & 7) + ((lane >> 4) & 1) * 8;
    const int kcl = ((lane >> 3) & 1) * 8;
    const uint32_t cB = (nwarp + nll) * WROWB + kcl * 2;

    float acc[2][8][4];
#pragma unroll
    for (int i = 0; i < 2; ++i)
#pragma unroll
        for (int j = 0; j < 8; ++j)
#pragma unroll
            for (int q = 0; q < 4; ++q) acc[i][j][q] = 0.f;

    auto issue_W = [&](int s) {
        const uint32_t wb = sb + (s & 1) * ST_SZ + ST_W;
        const int kk = s * BK;
#pragma unroll
        for (int r = 0; r < 4; ++r) {
            const int n = r * 128 + (tid >> 2);
            const int kc = tid & 3;
            cp_async16(wb + n * WROWB + kc * 16, g_Wh + (size_t)n * C_ + kk + kc * 8);
        }
        CP_COMMIT();
    };
    auto ldg_A = [&](int s, float4& f) {
        f = *(const float4*)(a_src + (size_t)s * BK * TH_);
    };
    auto sts_A = [&](int s, const float4& f) {
        const uint32_t ab = sb + (s & 1) * ST_SZ;
        uint32_t hi[2], lo[2];
        split4h((const float*)&f, hi, lo);
        sts64(ab + ST_A_H + a_sts_off, hi[0], hi[1]);
        sts64(ab + ST_A_L + a_sts_off, lo[0], lo[1]);
    };

    // ---- prologue ----
    {
        float4 f0;
        ldg_A(0, f0);
        issue_W(0);
        sts_A(0, f0);
        CP_WAIT(0);
        __syncthreads();
    }

    // ---- mainloop ----
    for (int s = 0; s < NS; ++s) {
        const bool pf = (s + 1 < NS);
        float4 fr;
        if (pf) { issue_W(s + 1); ldg_A(s + 1, fr); }

        const uint32_t stb = sb + (s & 1) * ST_SZ;
#pragma unroll
        for (int h16 = 0; h16 < 2; ++h16) {
            uint32_t aH[2][4], aL[2][4];
#pragma unroll
            for (int i = 0; i < 2; ++i) {
                ldm_x4_t(aH[i], stb + ST_A_H + h16 * 2048 + cA[i]);
                ldm_x4_t(aL[i], stb + ST_A_L + h16 * 2048 + cA[i]);
            }
#pragma unroll
            for (int j2 = 0; j2 < 4; ++j2) {
                uint32_t bH[4];
                ldm_x4(bH, stb + ST_W + cB + j2 * (16 * WROWB) + h16 * 32);
#pragma unroll
                for (int i = 0; i < 2; ++i)
#pragma unroll
                    for (int jj = 0; jj < 2; ++jj) {
                        float* d = acc[i][j2 * 2 + jj];
                        mma16816(d, aH[i], &bH[jj * 2]);
                        mma16816(d, aL[i], &bH[jj * 2]);
                    }
            }
        }
        if (pf) {
            sts_A(s + 1, fr);
            CP_WAIT(0);
        }
        __syncthreads();
    }

    // ---- in-kernel epilogue ----
    const float a2 = *prelu2_a;
    float2 spv[8];
#pragma unroll
    for (int j = 0; j < 8; ++j)
        spv[j] = *(const float2*)&g_sproj[bi * OUT_ + nwarp + j * 8 + (lane & 3) * 2];

    float su[4] = {0.f, 0.f, 0.f, 0.f}, sq[4] = {0.f, 0.f, 0.f, 0.f};
#pragma unroll
    for (int i = 0; i < 2; ++i)
#pragma unroll
        for (int j = 0; j < 8; ++j)
#pragma unroll
            for (int q = 0; q < 4; ++q) {
                float v = acc[i][j][q] + ((q & 1) ? spv[j].y : spv[j].x);
                v = (v >= 0.f) ? v : a2 * v;
                acc[i][j][q] = v;
                const int si = i * 2 + (q >> 1);
                su[si] += v; sq[si] += v * v;
            }
#pragma unroll
    for (int si = 0; si < 4; ++si) {
#pragma unroll
        for (int off = 1; off <= 2; off <<= 1) {
            su[si] += __shfl_xor_sync(0xffffffffu, su[si], off);
            sq[si] += __shfl_xor_sync(0xffffffffu, sq[si], off);
        }
    }
    if ((lane & 3) == 0) {
#pragma unroll
        for (int si = 0; si < 4; ++si) {
            const int tok = mwarp + (si >> 1) * 16 + (si & 1) * 8 + (lane >> 2);
            smf[PART_F + wn * 128 + tok * 2] = su[si];
            smf[PART_F + wn * 128 + tok * 2 + 1] = sq[si];
        }
    }
#pragma unroll
    for (int i = 0; i < 2; ++i) {
        const int tok = mwarp + i * 16 + (lane >> 2);
#pragma unroll
        for (int j = 0; j < 8; ++j) {
            const int c = nwarp + j * 8 + (lane & 3) * 2;
            *(float2*)&smf[tok * EZS + c] = make_float2(acc[i][j][0], acc[i][j][1]);
            *(float2*)&smf[(tok + 8) * EZS + c] = make_float2(acc[i][j][2], acc[i][j][3]);
        }
    }
    __syncthreads();

    if (tid < 64) {
        float s0 = 0.f, s1 = 0.f;
#pragma unroll
        for (int w = 0; w < 8; ++w) {
            s0 += smf[PART_F + w * 128 + tid * 2];
            s1 += smf[PART_F + w * 128 + tid * 2 + 1];
        }
        const float mu = s0 * (1.f / 512.f);
        smf[MU_F + tid] = mu;
        smf[RS_F + tid] = rsqrtf(s1 * (1.f / 512.f) - mu * mu + 1e-8f);
    }
    __syncthreads();

    {
        const int o = tid;
        const float lw = lnw[o], lb = lnb[o];
        const size_t gbase = ((size_t)(bi * OUT_ + o)) * TH_ + mb;
#pragma unroll 4
        for (int mq = 0; mq < BM; mq += 4) {
            float4 xv = *(const float4*)(x + gbase + mq);
            float4 yv;
            yv.x = xv.x + (smf[(mq + 0) * EZS + o] - smf[MU_F + mq + 0]) * smf[RS_F + mq + 0] * lw + lb;
            yv.y = xv.y + (smf[(mq + 1) * EZS + o] - smf[MU_F + mq + 1]) * smf[RS_F + mq + 1] * lw + lb;
            yv.z = xv.z + (smf[(mq + 2) * EZS + o] - smf[MU_F + mq + 2]) * smf[RS_F + mq + 2] * lw + lb;
            yv.w = xv.w + (smf[(mq + 3) * EZS + o] - smf[MU_F + mq + 3]) * smf[RS_F + mq + 3] * lw + lb;
            *(float4*)(out + gbase + mq) = yv;
        }
    }
}

// ---------------- launch ----------------
extern "C" void kernel_launch(void* const* d_in, const int* in_sizes, int n_in,
                              void* d_out, int out_size) {
    (void)in_sizes; (void)n_in; (void)out_size;
    const float* x        = (const float*)d_in[0];
    const float* s        = (const float*)d_in[1];
    const float* W        = (const float*)d_in[5];
    const float* bias     = (const float*)d_in[6];
    const float* prelu2_a = (const float*)d_in[7];
    const float* ln2_w    = (const float*)d_in[8];
    const float* ln2_b    = (const float*)d_in[9];
    float* out = (float*)d_out;

    cudaFuncSetAttribute(fused_kernel, cudaFuncAttributeMaxDynamicSharedMemorySize, SMEM_TOTAL);

    sproj_kernel<<<dim3(B_, OUT_ / 64), 256>>>(s, W, bias);
    wprep_kernel<<<OUT_, 256>>>(W);
    fused_kernel<<<MTOT_ / BM, NTHR, SMEM_TOTAL>>>(x, prelu2_a, ln2_w, ln2_b, out);
}